// round 3
// baseline (speedup 1.0000x reference)
#include <cuda_runtime.h>

// CounterfactualMultiheadAttention — algebraically collapsed.
// softmax rows sum to 1 (±1ulp) and the nonzero pattern is exactly !mask[b,k]:
//   attn_weights[b,h,q,k] = !mask[b,k] / cnt_b          (independent of h,q,Q,K)
//   ctx[b,q,:] = (1/cnt_b) * sum_{k unmasked} V[b,k,:]  (independent of q)
//   output[b,q,:] = ((colsum_value[b] @ Wv^T)/cnt_b + bv) @ Wo^T + bo
// All QKV GEMMs + attention GEMMs + softmax vanish; kernel is write-bound
// (~272 MB STG). Expected ~40-55 us at the ~6.3 TB/s LTS ceiling.

#define B 4
#define L 1024
#define D 1024
#define H 16
#define ROWCHUNKS 8

// Scratch (device globals; rewritten fresh every replay — no stale state)
__device__ float g_nzf[B][L];        // 1.0 if key unmasked else 0.0
__device__ float g_attn_row[B][L];   // nzf * inv_cnt
__device__ float g_inv_cnt[B];
__device__ float g_partial[B][ROWCHUNKS][D];
__device__ float g_ctx[B][D];
__device__ float g_outrow[B][D];

// ---------------------------------------------------------------------------
// K1: detect mask dtype (uint8 / int32 / float32), count unmasked, build rows.
// Probe reads only bytes [0,4096): in-bounds for all three dtypes.
//   float32 1.0f = 00 00 80 3F -> byte 0x3F at p%4==3   -> mode 2
//   uint8   1    -> nonzero bytes at p%4!=0              -> mode 1
//   int32   1    -> nonzero only at p%4==0               -> mode 0
// Deterministic for this dataset (mask = randint(0,2): both values present).
// ---------------------------------------------------------------------------
__global__ void k_mask(const void* __restrict__ mask) {
    __shared__ int sFloat, sOff, sCnt;
    const int t = threadIdx.x;
    const int b = blockIdx.x;
    if (t == 0) { sFloat = 0; sOff = 0; sCnt = 0; }
    __syncthreads();

    const unsigned char* bytes = (const unsigned char*)mask;
    int f = 0, o = 0;
    for (int p = t; p < B * L; p += blockDim.x) {
        unsigned char v = bytes[p];
        int r = p & 3;
        if (r == 3 && v == 0x3F) f = 1;
        if (r != 0 && v != 0)    o = 1;
    }
    if (f) atomicOr(&sFloat, 1);
    if (o) atomicOr(&sOff, 1);
    __syncthreads();
    const int mode = sFloat ? 2 : (sOff ? 1 : 0);

    int cnt = 0;
    for (int k = t; k < L; k += blockDim.x) {
        int g = b * L + k;
        bool m;
        if (mode == 2)      m = ((const float*)mask)[g] != 0.0f;
        else if (mode == 1) m = bytes[g] != 0;
        else                m = ((const int*)mask)[g] != 0;
        cnt += m ? 0 : 1;
    }
    atomicAdd(&sCnt, cnt);
    __syncthreads();

    const float inv = 1.0f / (float)max(sCnt, 1);
    if (t == 0) g_inv_cnt[b] = inv;
    for (int k = t; k < L; k += blockDim.x) {
        int g = b * L + k;
        bool m;
        if (mode == 2)      m = ((const float*)mask)[g] != 0.0f;
        else if (mode == 1) m = bytes[g] != 0;
        else                m = ((const int*)mask)[g] != 0;
        float nz = m ? 0.0f : 1.0f;
        g_nzf[b][k] = nz;
        g_attn_row[b][k] = nz * inv;
    }
}

// ---------------------------------------------------------------------------
// K2: masked partial column-sums of value[b,:,:] (16 MB stream).
// grid = (D/256, ROWCHUNKS, B): 128 rows per partial, coalesced columns.
// ---------------------------------------------------------------------------
__global__ void k_colsum_partial(const float* __restrict__ value) {
    const int c  = blockIdx.x * blockDim.x + threadIdx.x;  // column 0..1023
    const int rc = blockIdx.y;                             // row chunk 0..7
    const int b  = blockIdx.z;
    const int rows = L / ROWCHUNKS;                        // 128
    const float* vp = value + ((size_t)b * L + (size_t)rc * rows) * D + c;
    const float* nz = &g_nzf[b][rc * rows];
    float s = 0.0f;
#pragma unroll 8
    for (int r = 0; r < rows; r++)
        s += vp[(size_t)r * D] * nz[r];
    g_partial[b][rc][c] = s;
}

// ---------------------------------------------------------------------------
// K3: GEMV vs Wv with inline partial reduction. One warp per output row;
// 4 batch accumulators share each weight load (Wv read once: 4 MB).
// ---------------------------------------------------------------------------
__global__ void k_gemv_v(const float* __restrict__ Wv, const float* __restrict__ bv) {
    const int warp = (blockIdx.x * blockDim.x + threadIdx.x) >> 5;
    const int lane = threadIdx.x & 31;
    if (warp >= D) return;
    const float* wrow = Wv + (size_t)warp * D;
    float a0 = 0, a1 = 0, a2 = 0, a3 = 0;
#pragma unroll 4
    for (int i = 0; i < D; i += 32) {
        int c = i + lane;
        float w = wrow[c];
        float s0 = 0, s1 = 0, s2 = 0, s3 = 0;
#pragma unroll
        for (int rc = 0; rc < ROWCHUNKS; rc++) {   // inline colsum reduce (L2 hits)
            s0 += g_partial[0][rc][c];
            s1 += g_partial[1][rc][c];
            s2 += g_partial[2][rc][c];
            s3 += g_partial[3][rc][c];
        }
        a0 += w * s0; a1 += w * s1; a2 += w * s2; a3 += w * s3;
    }
#pragma unroll
    for (int off = 16; off; off >>= 1) {
        a0 += __shfl_down_sync(0xFFFFFFFFu, a0, off);
        a1 += __shfl_down_sync(0xFFFFFFFFu, a1, off);
        a2 += __shfl_down_sync(0xFFFFFFFFu, a2, off);
        a3 += __shfl_down_sync(0xFFFFFFFFu, a3, off);
    }
    if (lane == 0) {
        float bb = bv[warp];
        g_ctx[0][warp] = a0 * g_inv_cnt[0] + bb;
        g_ctx[1][warp] = a1 * g_inv_cnt[1] + bb;
        g_ctx[2][warp] = a2 * g_inv_cnt[2] + bb;
        g_ctx[3][warp] = a3 * g_inv_cnt[3] + bb;
    }
}

// K4: GEMV vs Wo (depends on g_ctx).
__global__ void k_gemv_o(const float* __restrict__ Wo, const float* __restrict__ bo) {
    const int warp = (blockIdx.x * blockDim.x + threadIdx.x) >> 5;
    const int lane = threadIdx.x & 31;
    if (warp >= D) return;
    const float* wrow = Wo + (size_t)warp * D;
    float a0 = 0, a1 = 0, a2 = 0, a3 = 0;
#pragma unroll 4
    for (int i = 0; i < D; i += 32) {
        int c = i + lane;
        float w = wrow[c];
        a0 += w * g_ctx[0][c];
        a1 += w * g_ctx[1][c];
        a2 += w * g_ctx[2][c];
        a3 += w * g_ctx[3][c];
    }
#pragma unroll
    for (int off = 16; off; off >>= 1) {
        a0 += __shfl_down_sync(0xFFFFFFFFu, a0, off);
        a1 += __shfl_down_sync(0xFFFFFFFFu, a1, off);
        a2 += __shfl_down_sync(0xFFFFFFFFu, a2, off);
        a3 += __shfl_down_sync(0xFFFFFFFFu, a3, off);
    }
    if (lane == 0) {
        float bb = bo[warp];
        g_outrow[0][warp] = a0 + bb;
        g_outrow[1][warp] = a1 + bb;
        g_outrow[2][warp] = a2 + bb;
        g_outrow[3][warp] = a3 + bb;
    }
}

// ---------------------------------------------------------------------------
// K5a: output[b,q,:] = g_outrow[b]   (4M floats). 2 streaming float4/thread.
// K5b: attn[b,h,q,:] = g_attn_row[b] (64M floats). 2 streaming float4/thread.
// Source rows are L1-broadcast hits; stores use .cs (no reuse, evict-first).
// ---------------------------------------------------------------------------
__global__ void k_write_out(float4* __restrict__ out) {
    unsigned idx = blockIdx.x * blockDim.x + threadIdx.x;     // < 2^19
    unsigned o4 = idx & 255u;
    unsigned b0 = idx >> 18, b1 = (idx + (1u << 19)) >> 18;
    __stcs(out + idx,              ((const float4*)g_outrow[b0])[o4]);
    __stcs(out + idx + (1u << 19), ((const float4*)g_outrow[b1])[o4]);
}

__global__ void k_write_attn(float4* __restrict__ out) {
    unsigned idx = blockIdx.x * blockDim.x + threadIdx.x;     // < 2^23
    unsigned k4 = idx & 255u;
    unsigned b0 = idx >> 22, b1 = (idx + (1u << 23)) >> 22;
    __stcs(out + idx,              ((const float4*)g_attn_row[b0])[k4]);
    __stcs(out + idx + (1u << 23), ((const float4*)g_attn_row[b1])[k4]);
}

// Fallback writers for unexpected out_size (element-exact, guarded)
__global__ void k_write_attn_n(float4* __restrict__ out, unsigned n4) {
    unsigned idx = blockIdx.x * blockDim.x + threadIdx.x;
    if (idx >= n4) return;
    unsigned k4 = idx & 255u;
    unsigned b  = (idx >> 22) & 3u;
    __stcs(out + idx, ((const float4*)g_attn_row[b])[k4]);
}
__global__ void k_write_out_n(float4* __restrict__ out, unsigned n4) {
    unsigned idx = blockIdx.x * blockDim.x + threadIdx.x;
    if (idx >= n4) return;
    unsigned o4 = idx & 255u;
    unsigned b  = (idx >> 18) & 3u;
    __stcs(out + idx, ((const float4*)g_outrow[b])[o4]);
}

// ---------------------------------------------------------------------------
extern "C" void kernel_launch(void* const* d_in, const int* in_sizes, int n_in,
                              void* d_out, int out_size) {
    const float* value = (const float*)d_in[2];
    const void*  mask  = d_in[3];
    const float* Wv    = (const float*)d_in[8];
    const float* bv    = (const float*)d_in[9];
    const float* Wo    = (const float*)d_in[10];
    const float* bo    = (const float*)d_in[11];
    float* out = (float*)d_out;

    k_mask<<<B, 256>>>(mask);
    k_colsum_partial<<<dim3(D / 256, ROWCHUNKS, B), 256>>>(value);
    k_gemv_v<<<(D * 32) / 256, 256>>>(Wv, bv);
    k_gemv_o<<<(D * 32) / 256, 256>>>(Wo, bo);

    const int OUT_N  = B * L * D;          //  4,194,304
    const int ATTN_N = B * H * L * L;      // 67,108,864

    if (out_size == OUT_N + ATTN_N) {
        k_write_out <<<(1 << 19) / 256, 256>>>((float4*)out);
        k_write_attn<<<(1 << 23) / 256, 256>>>((float4*)(out + OUT_N));
    } else if (out_size == ATTN_N) {
        k_write_attn<<<(1 << 23) / 256, 256>>>((float4*)out);
    } else if (out_size == OUT_N) {
        k_write_out<<<(1 << 19) / 256, 256>>>((float4*)out);
    } else if (out_size > OUT_N) {  // unexpected: out then attn, size-guarded
        unsigned n4o = OUT_N / 4;
        unsigned n4a = (unsigned)((out_size - OUT_N) / 4);
        if (n4a > (unsigned)(ATTN_N / 4)) n4a = ATTN_N / 4;
        k_write_out_n <<<(n4o + 255) / 256, 256>>>((float4*)out, n4o);
        k_write_attn_n<<<(n4a + 255) / 256, 256>>>((float4*)(out + OUT_N), n4a);
    } else {
        unsigned n4o = (unsigned)(out_size / 4);
        k_write_out_n<<<(n4o + 255) / 256, 256>>>((float4*)out, n4o);
    }
}

// round 5
// speedup vs baseline: 1.4512x; 1.4512x over previous
#include <cuda_runtime.h>

// CounterfactualMultiheadAttention — algebraically collapsed.
//   attn_weights[b,h,q,k] = !mask[b,k] / cnt_b          (independent of h,q,Q,K)
//   output[b,q,:] = ((colsum_value[b] @ Wv^T)/cnt_b + bv) @ Wo^T + bo   (independent of q)
// Pipeline: colsum -> gemv_v -> gemv_o -> write_all(attn 256MB + out 16MB).
// Short serial prefix first; the single store-bound giant last.

#define B 4
#define L 1024
#define D 1024
#define H 16
#define ROWCHUNKS 8
#define NBLK_COL 128            // colsum partial blocks (4 c-blks * 8 rc * 4 b)
#define NBLK_OUT 256            // out writer blocks   (2^20 float4 / 4096)
#define NBLK_ATTN 2048          // attn writer blocks  (2^24 float4 / 8192)

__device__ float g_partial[B][ROWCHUNKS][D];
__device__ float g_ctx[B][D];
__device__ float g_outrow[B][D];

// mask dtype decode: mode 0=int32, 1=uint8, 2=float32
__device__ __forceinline__ bool mask_test(const void* mask, int mode, int g) {
    if (mode == 2) return ((const float*)mask)[g] != 0.0f;
    if (mode == 1) return ((const unsigned char*)mask)[g] != 0;
    return ((const int*)mask)[g] != 0;
}

// Per-block dtype probe over bytes [0,4096) (in-bounds for all 3 dtypes).
// float32 1.0f = 00 00 80 3F -> 0x3F at p%4==3; uint8 -> nonzero at p%4!=0.
// Deterministic for this dataset (mask = randint(0,2): both values present).
__device__ __forceinline__ void probe_flags(const void* mask, int tid,
                                            int* sFloat, int* sOff) {
    const unsigned char* bytes = (const unsigned char*)mask;
    int f = 0, o = 0;
#pragma unroll
    for (int i = 0; i < 16; i++) {
        unsigned char v = bytes[tid * 16 + i];
        int r = i & 3;                 // (tid*16+i)&3 == i&3
        if (r == 3 && v == 0x3F) f = 1;
        if (r != 0 && v != 0)    o = 1;
    }
    if (f) atomicOr(sFloat, 1);
    if (o) atomicOr(sOff, 1);
}

// ---------------------------------------------------------------------------
// K1: masked partial column-sums of value (16 MB read). 128 blocks.
// ---------------------------------------------------------------------------
__global__ void __launch_bounds__(256)
k_colsum(const float* __restrict__ value, const void* __restrict__ mask) {
    __shared__ int sFloat, sOff;
    const int tid = threadIdx.x;
    if (tid == 0) { sFloat = 0; sOff = 0; }
    __syncthreads();
    probe_flags(mask, tid, &sFloat, &sOff);
    __syncthreads();
    const int mode = sFloat ? 2 : (sOff ? 1 : 0);

    const int cb = blockIdx.x;
    const int c  = (cb & 3) * 256 + tid;
    const int rc = (cb >> 2) & 7;
    const int b  = cb >> 5;
    const float* vp = value + ((size_t)b * L + rc * 128) * D + c;
    const int gbase = b * L + rc * 128;
    float s = 0.0f;
#pragma unroll 8
    for (int r = 0; r < 128; r++) {
        float nz = mask_test(mask, mode, gbase + r) ? 0.0f : 1.0f;
        s += vp[(size_t)r * D] * nz;
    }
    g_partial[b][rc][c] = s;
}

// ---------------------------------------------------------------------------
// K2: gemv vs Wv. 128 blocks x 256 threads; prologue reduces g_partial into
// shared (float4, high MLP) and recomputes counts; each warp streams one
// weight row as 8 independent LDG.128.
// ---------------------------------------------------------------------------
__global__ void __launch_bounds__(256)
k_gemv_v(const float* __restrict__ Wv, const float* __restrict__ bv,
         const void* __restrict__ mask) {
    __shared__ int sFloat, sOff;
    __shared__ int scnt[B];
    __shared__ float4 sh[B][256];
    const int tid = threadIdx.x, lane = tid & 31, warp = tid >> 5;
    if (tid == 0) { sFloat = 0; sOff = 0; }
    if (tid < B) scnt[tid] = 0;
    __syncthreads();
    probe_flags(mask, tid, &sFloat, &sOff);
    __syncthreads();
    const int mode = sFloat ? 2 : (sOff ? 1 : 0);

    // counts: thread covers 16 mask entries, all within batch tid>>6
    {
        int c = 0;
#pragma unroll
        for (int i = 0; i < 16; i++)
            c += mask_test(mask, mode, tid * 16 + i) ? 0 : 1;
        atomicAdd(&scnt[tid >> 6], c);
    }
    // reduce partials into shared
#pragma unroll
    for (int b = 0; b < B; b++) {
        float4 a = make_float4(0.f, 0.f, 0.f, 0.f);
#pragma unroll
        for (int rc = 0; rc < ROWCHUNKS; rc++) {
            float4 p = ((const float4*)g_partial[b][rc])[tid];
            a.x += p.x; a.y += p.y; a.z += p.z; a.w += p.w;
        }
        sh[b][tid] = a;
    }
    __syncthreads();

    const int row = blockIdx.x * 8 + warp;
    const float4* wr = (const float4*)(Wv + (size_t)row * D);
    float a0 = 0, a1 = 0, a2 = 0, a3 = 0;
#pragma unroll
    for (int j = 0; j < 8; j++) {
        float4 w  = wr[lane + j * 32];
        float4 x0 = sh[0][lane + j * 32];
        float4 x1 = sh[1][lane + j * 32];
        float4 x2 = sh[2][lane + j * 32];
        float4 x3 = sh[3][lane + j * 32];
        a0 += w.x * x0.x + w.y * x0.y + w.z * x0.z + w.w * x0.w;
        a1 += w.x * x1.x + w.y * x1.y + w.z * x1.z + w.w * x1.w;
        a2 += w.x * x2.x + w.y * x2.y + w.z * x2.z + w.w * x2.w;
        a3 += w.x * x3.x + w.y * x3.y + w.z * x3.z + w.w * x3.w;
    }
#pragma unroll
    for (int off = 16; off; off >>= 1) {
        a0 += __shfl_down_sync(0xFFFFFFFFu, a0, off);
        a1 += __shfl_down_sync(0xFFFFFFFFu, a1, off);
        a2 += __shfl_down_sync(0xFFFFFFFFu, a2, off);
        a3 += __shfl_down_sync(0xFFFFFFFFu, a3, off);
    }
    if (lane == 0) {
        float bb = bv[row];
        g_ctx[0][row] = a0 / (float)max(scnt[0], 1) + bb;
        g_ctx[1][row] = a1 / (float)max(scnt[1], 1) + bb;
        g_ctx[2][row] = a2 / (float)max(scnt[2], 1) + bb;
        g_ctx[3][row] = a3 / (float)max(scnt[3], 1) + bb;
    }
}

// K3: gemv vs Wo (same shape, vector = g_ctx staged in shared).
__global__ void __launch_bounds__(256)
k_gemv_o(const float* __restrict__ Wo, const float* __restrict__ bo) {
    __shared__ float4 sh[B][256];
    const int tid = threadIdx.x, lane = tid & 31, warp = tid >> 5;
#pragma unroll
    for (int b = 0; b < B; b++)
        sh[b][tid] = ((const float4*)g_ctx[b])[tid];
    __syncthreads();

    const int row = blockIdx.x * 8 + warp;
    const float4* wr = (const float4*)(Wo + (size_t)row * D);
    float a0 = 0, a1 = 0, a2 = 0, a3 = 0;
#pragma unroll
    for (int j = 0; j < 8; j++) {
        float4 w  = wr[lane + j * 32];
        float4 x0 = sh[0][lane + j * 32];
        float4 x1 = sh[1][lane + j * 32];
        float4 x2 = sh[2][lane + j * 32];
        float4 x3 = sh[3][lane + j * 32];
        a0 += w.x * x0.x + w.y * x0.y + w.z * x0.z + w.w * x0.w;
        a1 += w.x * x1.x + w.y * x1.y + w.z * x1.z + w.w * x1.w;
        a2 += w.x * x2.x + w.y * x2.y + w.z * x2.z + w.w * x2.w;
        a3 += w.x * x3.x + w.y * x3.y + w.z * x3.z + w.w * x3.w;
    }
#pragma unroll
    for (int off = 16; off; off >>= 1) {
        a0 += __shfl_down_sync(0xFFFFFFFFu, a0, off);
        a1 += __shfl_down_sync(0xFFFFFFFFu, a1, off);
        a2 += __shfl_down_sync(0xFFFFFFFFu, a2, off);
        a3 += __shfl_down_sync(0xFFFFFFFFu, a3, off);
    }
    if (lane == 0) {
        float bb = bo[row];
        g_outrow[0][row] = a0 + bb;
        g_outrow[1][row] = a1 + bb;
        g_outrow[2][row] = a2 + bb;
        g_outrow[3][row] = a3 + bb;
    }
}

// ---------------------------------------------------------------------------
// K4: all broadcast writes in one kernel (272 MB streaming STG.128).
//   blocks [0,256)        : output[b,q,:] = g_outrow[b]     (16 MB)
//   blocks [256,256+2048) : attn[b,h,q,:] = !mask/cnt       (256 MB)
// Per-thread store value is loop-invariant; mask/count recomputed per attn
// block from the 4 KB mask (L2 broadcast, free vs 128 KB of stores).
// ---------------------------------------------------------------------------
__global__ void __launch_bounds__(256)
k_write_all(float4* __restrict__ out, float4* __restrict__ attn,
            const void* __restrict__ mask) {
    const int tid = threadIdx.x;

    if (blockIdx.x < NBLK_OUT) {
        const int b = blockIdx.x >> 6;             // 64 blocks per batch
        const float4 v = ((const float4*)g_outrow[b])[tid];
        float4* p = out + blockIdx.x * 4096u + tid;
#pragma unroll
        for (int j = 0; j < 16; j++)
            __stcs(p + j * 256u, v);
        return;
    }

    __shared__ int sFloat, sOff, sCnt;
    if (tid == 0) { sFloat = 0; sOff = 0; sCnt = 0; }
    __syncthreads();
    probe_flags(mask, tid, &sFloat, &sOff);
    __syncthreads();
    const int mode = sFloat ? 2 : (sOff ? 1 : 0);

    const unsigned abi = blockIdx.x - NBLK_OUT;
    const int b = abi >> 9;                        // 512 blocks per batch
    const bool m0 = mask_test(mask, mode, b * L + tid * 4 + 0);
    const bool m1 = mask_test(mask, mode, b * L + tid * 4 + 1);
    const bool m2 = mask_test(mask, mode, b * L + tid * 4 + 2);
    const bool m3 = mask_test(mask, mode, b * L + tid * 4 + 3);
    int cnt = (!m0) + (!m1) + (!m2) + (!m3);       // 256 threads cover the row
    atomicAdd(&sCnt, cnt);
    __syncthreads();
    const float inv = 1.0f / (float)max(sCnt, 1);
    const float4 v = make_float4(m0 ? 0.0f : inv, m1 ? 0.0f : inv,
                                 m2 ? 0.0f : inv, m3 ? 0.0f : inv);
    float4* p = attn + abi * 8192u + tid;          // per-thread k4 == tid
#pragma unroll
    for (int j = 0; j < 32; j++)
        __stcs(p + j * 256u, v);
}

// ---------------- Fallback writers for unexpected out_size ------------------
__global__ void k_fb_attn(float4* __restrict__ out, unsigned n4,
                          const void* __restrict__ mask) {
    __shared__ int sFloat, sOff;
    __shared__ int scnt[B];
    const int tid = threadIdx.x;
    if (tid == 0) { sFloat = 0; sOff = 0; }
    if (tid < B) scnt[tid] = 0;
    __syncthreads();
    probe_flags(mask, tid, &sFloat, &sOff);
    __syncthreads();
    const int mode = sFloat ? 2 : (sOff ? 1 : 0);
    {
        int c = 0;
#pragma unroll
        for (int i = 0; i < 16; i++)
            c += mask_test(mask, mode, tid * 16 + i) ? 0 : 1;
        atomicAdd(&scnt[tid >> 6], c);
    }
    __syncthreads();
    unsigned idx = blockIdx.x * blockDim.x + tid;
    if (idx >= n4) return;
    int b = (idx >> 22) & 3;
    float inv = 1.0f / (float)max(scnt[b], 1);
    int k0 = (idx & 255u) * 4;
    float4 v;
    v.x = mask_test(mask, mode, b * L + k0 + 0) ? 0.0f : inv;
    v.y = mask_test(mask, mode, b * L + k0 + 1) ? 0.0f : inv;
    v.z = mask_test(mask, mode, b * L + k0 + 2) ? 0.0f : inv;
    v.w = mask_test(mask, mode, b * L + k0 + 3) ? 0.0f : inv;
    __stcs(out + idx, v);
}
__global__ void k_fb_out(float4* __restrict__ out, unsigned n4) {
    unsigned idx = blockIdx.x * blockDim.x + threadIdx.x;
    if (idx >= n4) return;
    unsigned o4 = idx & 255u;
    unsigned b  = (idx >> 18) & 3u;
    __stcs(out + idx, ((const float4*)g_outrow[b])[o4]);
}

// ---------------------------------------------------------------------------
extern "C" void kernel_launch(void* const* d_in, const int* in_sizes, int n_in,
                              void* d_out, int out_size) {
    const float* value = (const float*)d_in[2];
    const void*  mask  = d_in[3];
    const float* Wv    = (const float*)d_in[8];
    const float* bv    = (const float*)d_in[9];
    const float* Wo    = (const float*)d_in[10];
    const float* bo    = (const float*)d_in[11];
    float* out = (float*)d_out;

    const int OUT_N  = B * L * D;          //  4,194,304
    const int ATTN_N = B * H * L * L;      // 67,108,864

    k_colsum<<<NBLK_COL, 256>>>(value, mask);
    k_gemv_v<<<128, 256>>>(Wv, bv, mask);
    k_gemv_o<<<128, 256>>>(Wo, bo);

    if (out_size == OUT_N + ATTN_N) {
        k_write_all<<<NBLK_OUT + NBLK_ATTN, 256>>>((float4*)out,
                                                   (float4*)(out + OUT_N),
                                                   mask);
    } else if (out_size >= OUT_N) {   // robustness path (not expected)
        unsigned n4o = OUT_N / 4;
        k_fb_out<<<(n4o + 255) / 256, 256>>>((float4*)out, n4o);
        unsigned rem = (unsigned)((out_size - OUT_N) / 4);
        if (rem) {
            if (rem > (unsigned)(ATTN_N / 4)) rem = ATTN_N / 4;
            k_fb_attn<<<(rem + 255) / 256, 256>>>((float4*)(out + OUT_N),
                                                  rem, mask);
        }
    } else {
        unsigned n4o = (unsigned)(out_size / 4);
        if (n4o) k_fb_out<<<(n4o + 255) / 256, 256>>>((float4*)out, n4o);
    }
}